// round 1
// baseline (speedup 1.0000x reference)
#include <cuda_runtime.h>
#include <cuda_bf16.h>

// Problem constants
#define BB   2
#define LL   2048
#define DD   512
#define HH   16
#define DKK  32
#define BH   (BB * HH)        // 32
#define MTOT (BB * LL)        // 4096

// Scratch: Q,K,V,O in [b,h,l,dk] layout, 8 MB each (static device arrays:
// allocation inside kernel_launch is forbidden by the harness).
__device__ float g_Q[BH * LL * DKK];
__device__ float g_K[BH * LL * DKK];
__device__ float g_V[BH * LL * DKK];
__device__ float g_O[BH * LL * DKK];

// ---------------------------------------------------------------------------
// QKV projection GEMM: Out[b,h,l,dk] = (X @ W + bias)[b*L+l, h*32+dk]
// 64x64 tile, Ktile=16, 256 threads, 4x4 microtile.
// blockIdx.z in {0,1,2} selects (q,Wq),(k,Wk),(v,Wv).
// ---------------------------------------------------------------------------
__global__ __launch_bounds__(256)
void qkv_proj_kernel(const float* __restrict__ xq, const float* __restrict__ xk,
                     const float* __restrict__ xv,
                     const float* __restrict__ wq, const float* __restrict__ wk,
                     const float* __restrict__ wv,
                     const float* __restrict__ bq, const float* __restrict__ bk,
                     const float* __restrict__ bv)
{
    const float* A; const float* W; const float* bias; float* Out;
    if (blockIdx.z == 0)      { A = xq; W = wq; bias = bq; Out = g_Q; }
    else if (blockIdx.z == 1) { A = xk; W = wk; bias = bk; Out = g_K; }
    else                      { A = xv; W = wv; bias = bv; Out = g_V; }

    __shared__ __align__(16) float As[16][64];
    __shared__ __align__(16) float Bs[16][64];

    const int tid  = threadIdx.x;
    const int tx   = tid & 15;
    const int ty   = tid >> 4;
    const int m0   = blockIdx.y * 64;
    const int n0   = blockIdx.x * 64;
    const int lrow = tid >> 2;          // 0..63  (A tile row)
    const int lk4  = (tid & 3) << 2;    // 0,4,8,12 (A tile k offset)
    const int brow = tid >> 4;          // 0..15  (B tile k row)
    const int bn4  = (tid & 15) << 2;   // 0..60  (B tile n offset)

    float acc[4][4] = {};

    for (int k0 = 0; k0 < DD; k0 += 16) {
        float4 a4 = *(const float4*)(A + (size_t)(m0 + lrow) * DD + k0 + lk4);
        As[lk4 + 0][lrow] = a4.x;
        As[lk4 + 1][lrow] = a4.y;
        As[lk4 + 2][lrow] = a4.z;
        As[lk4 + 3][lrow] = a4.w;
        *(float4*)&Bs[brow][bn4] =
            *(const float4*)(W + (size_t)(k0 + brow) * DD + n0 + bn4);
        __syncthreads();
        #pragma unroll
        for (int k = 0; k < 16; k++) {
            float4 av = ((const float4*)As[k])[ty];
            float4 bv4 = ((const float4*)Bs[k])[tx];
            float a[4] = {av.x, av.y, av.z, av.w};
            float b[4] = {bv4.x, bv4.y, bv4.z, bv4.w};
            #pragma unroll
            for (int i = 0; i < 4; i++)
                #pragma unroll
                for (int j = 0; j < 4; j++)
                    acc[i][j] += a[i] * b[j];
        }
        __syncthreads();
    }

    // Epilogue: permuted store to [b,h,l,dk]
    const int n  = n0 + tx * 4;   // output feature (h*32+dk), 4 consecutive, same head
    const int h  = n >> 5;
    const int dk = n & 31;
    float4 b4 = *(const float4*)(bias + n);
    #pragma unroll
    for (int i = 0; i < 4; i++) {
        int m  = m0 + ty * 4 + i;
        int b_ = m >> 11;           // / L
        int l_ = m & (LL - 1);
        float4 o;
        o.x = acc[i][0] + b4.x;
        o.y = acc[i][1] + b4.y;
        o.z = acc[i][2] + b4.z;
        o.w = acc[i][3] + b4.w;
        *(float4*)(Out + (((size_t)(b_ * HH + h)) * LL + l_) * DKK + dk) = o;
    }
}

// ---------------------------------------------------------------------------
// Flash attention: 1 thread = 1 query row, K/V tiles of 32 rows in smem.
// All threads walk (j,d) uniformly -> all smem reads are broadcasts.
// grid = (L/128, B*H), 128 threads.
// ---------------------------------------------------------------------------
__global__ __launch_bounds__(128)
void attn_kernel(const int* __restrict__ mask)
{
    __shared__ __align__(16) float Ks[32][32];
    __shared__ __align__(16) float Vs[32][32];

    const int bh = blockIdx.y;          // 0..31
    const int b_ = bh >> 4;             // / H
    const int t  = threadIdx.x;
    const int q  = blockIdx.x * 128 + t;

    const float* Qp = g_Q + ((size_t)bh * LL + q) * DKK;
    float qr[DKK];
    #pragma unroll
    for (int d = 0; d < DKK; d += 4) {
        float4 v4 = *(const float4*)(Qp + d);
        qr[d] = v4.x; qr[d + 1] = v4.y; qr[d + 2] = v4.z; qr[d + 3] = v4.w;
    }

    const int* mrow = mask + ((size_t)b_ * LL + q) * LL;
    const float scale = 0.17677669529663687f;   // 1/sqrt(32)

    float mx = -3e38f, lsum = 0.f;
    float acc[DKK];
    #pragma unroll
    for (int d = 0; d < DKK; d++) acc[d] = 0.f;

    const float* Kbase = g_K + (size_t)bh * LL * DKK;
    const float* Vbase = g_V + (size_t)bh * LL * DKK;

    for (int kt = 0; kt < LL; kt += 32) {
        // Load K/V tile (32x32 floats each = 256 float4 each; 2 per thread)
        #pragma unroll
        for (int i = 0; i < 2; i++) {
            int idx = t + i * 128;       // 0..255
            int r = idx >> 3, c = (idx & 7) << 2;
            *(float4*)&Ks[r][c] = *(const float4*)(Kbase + (size_t)(kt + r) * DKK + c);
            *(float4*)&Vs[r][c] = *(const float4*)(Vbase + (size_t)(kt + r) * DKK + c);
        }
        __syncthreads();

        // Scores for this thread's query row
        float s[32];
        #pragma unroll
        for (int j = 0; j < 32; j++) {
            float sv = 0.f;
            #pragma unroll
            for (int d = 0; d < DKK; d += 4) {
                float4 kv = *(const float4*)&Ks[j][d];
                sv += qr[d] * kv.x + qr[d + 1] * kv.y
                    + qr[d + 2] * kv.z + qr[d + 3] * kv.w;
            }
            s[j] = sv;
        }

        // Mask + scale (masked logits are exactly -1e9, matching reference)
        #pragma unroll
        for (int j = 0; j < 32; j += 4) {
            int4 mv = *(const int4*)(mrow + kt + j);
            s[j + 0] = mv.x ? s[j + 0] * scale : -1e9f;
            s[j + 1] = mv.y ? s[j + 1] * scale : -1e9f;
            s[j + 2] = mv.z ? s[j + 2] * scale : -1e9f;
            s[j + 3] = mv.w ? s[j + 3] * scale : -1e9f;
        }

        // Online softmax update
        float mnew = mx;
        #pragma unroll
        for (int j = 0; j < 32; j++) mnew = fmaxf(mnew, s[j]);
        float corr = __expf(mx - mnew);
        mx = mnew;
        lsum *= corr;
        #pragma unroll
        for (int d = 0; d < DKK; d++) acc[d] *= corr;

        #pragma unroll
        for (int j = 0; j < 32; j++) {
            float p = __expf(s[j] - mx);
            lsum += p;
            #pragma unroll
            for (int d = 0; d < DKK; d += 4) {
                float4 vv = *(const float4*)&Vs[j][d];
                acc[d]     += p * vv.x;
                acc[d + 1] += p * vv.y;
                acc[d + 2] += p * vv.z;
                acc[d + 3] += p * vv.w;
            }
        }
        __syncthreads();
    }

    float inv = 1.f / lsum;
    float* Op = g_O + ((size_t)bh * LL + q) * DKK;
    #pragma unroll
    for (int d = 0; d < DKK; d += 4) {
        float4 o;
        o.x = acc[d] * inv; o.y = acc[d + 1] * inv;
        o.z = acc[d + 2] * inv; o.w = acc[d + 3] * inv;
        *(float4*)(Op + d) = o;
    }
}

// ---------------------------------------------------------------------------
// Output projection: out[b,l,:] = concat_heads(O)[b,l,:] @ Wo + bo
// Same GEMM; A is gathered from [b,h,l,dk] layout.
// ---------------------------------------------------------------------------
__global__ __launch_bounds__(256)
void out_proj_kernel(const float* __restrict__ wo, const float* __restrict__ bo,
                     float* __restrict__ out)
{
    __shared__ __align__(16) float As[16][64];
    __shared__ __align__(16) float Bs[16][64];

    const int tid  = threadIdx.x;
    const int tx   = tid & 15;
    const int ty   = tid >> 4;
    const int m0   = blockIdx.y * 64;
    const int n0   = blockIdx.x * 64;
    const int lrow = tid >> 2;
    const int lk4  = (tid & 3) << 2;
    const int brow = tid >> 4;
    const int bn4  = (tid & 15) << 2;

    // Gathered A row base: m -> (b,l)
    const int m_  = m0 + lrow;
    const int ab  = m_ >> 11;
    const int al  = m_ & (LL - 1);

    float acc[4][4] = {};

    for (int k0 = 0; k0 < DD; k0 += 16) {
        int kk = k0 + lk4;            // 4 consecutive, same head
        int h  = kk >> 5;
        int dk = kk & 31;
        float4 a4 = *(const float4*)(g_O +
            (((size_t)(ab * HH + h)) * LL + al) * DKK + dk);
        As[lk4 + 0][lrow] = a4.x;
        As[lk4 + 1][lrow] = a4.y;
        As[lk4 + 2][lrow] = a4.z;
        As[lk4 + 3][lrow] = a4.w;
        *(float4*)&Bs[brow][bn4] =
            *(const float4*)(wo + (size_t)(k0 + brow) * DD + n0 + bn4);
        __syncthreads();
        #pragma unroll
        for (int k = 0; k < 16; k++) {
            float4 av = ((const float4*)As[k])[ty];
            float4 bv4 = ((const float4*)Bs[k])[tx];
            float a[4] = {av.x, av.y, av.z, av.w};
            float b[4] = {bv4.x, bv4.y, bv4.z, bv4.w};
            #pragma unroll
            for (int i = 0; i < 4; i++)
                #pragma unroll
                for (int j = 0; j < 4; j++)
                    acc[i][j] += a[i] * b[j];
        }
        __syncthreads();
    }

    const int n = n0 + tx * 4;
    float4 b4 = *(const float4*)(bo + n);
    #pragma unroll
    for (int i = 0; i < 4; i++) {
        int m = m0 + ty * 4 + i;
        float4 o;
        o.x = acc[i][0] + b4.x;
        o.y = acc[i][1] + b4.y;
        o.z = acc[i][2] + b4.z;
        o.w = acc[i][3] + b4.w;
        *(float4*)(out + (size_t)m * DD + n) = o;
    }
}

// ---------------------------------------------------------------------------
// Inputs (metadata order): 0 q, 1 k, 2 v, 3 mask(int32), 4 is_training,
// 5 wq, 6 bq, 7 wk, 8 bk, 9 wv, 10 bv, 11 wo, 12 bo
// ---------------------------------------------------------------------------
extern "C" void kernel_launch(void* const* d_in, const int* in_sizes, int n_in,
                              void* d_out, int out_size)
{
    const float* q    = (const float*)d_in[0];
    const float* k    = (const float*)d_in[1];
    const float* v    = (const float*)d_in[2];
    const int*   mask = (const int*)  d_in[3];
    const float* wq   = (const float*)d_in[5];
    const float* bq   = (const float*)d_in[6];
    const float* wk   = (const float*)d_in[7];
    const float* bk   = (const float*)d_in[8];
    const float* wv   = (const float*)d_in[9];
    const float* bv   = (const float*)d_in[10];
    const float* wo   = (const float*)d_in[11];
    const float* bo   = (const float*)d_in[12];
    float* out = (float*)d_out;

    dim3 g1(DD / 64, MTOT / 64, 3);
    qkv_proj_kernel<<<g1, 256>>>(q, k, v, wq, wk, wv, bq, bk, bv);

    dim3 g2(LL / 128, BH);
    attn_kernel<<<g2, 128>>>(mask);

    dim3 g3(DD / 64, MTOT / 64);
    out_proj_kernel<<<g3, 256>>>(wo, bo, out);
}

// round 4
// speedup vs baseline: 1.7614x; 1.7614x over previous
#include <cuda_runtime.h>
#include <cuda_bf16.h>
#include <cstdint>

// Problem constants
#define BB   2
#define LL   2048
#define DD   512
#define HH   16
#define DKK  32
#define BH   (BB * HH)        // 32
#define MTOT (BB * LL)        // 4096

// Scratch (static device arrays; allocation in kernel_launch is forbidden)
__device__ float    g_Q  [BH * LL * DKK];   // [bh][l][dk] fp32
__device__ float    g_Khi[BH * LL * DKK];   // [bh][l][dk] tf32-hi
__device__ float    g_Klo[BH * LL * DKK];   // tf32-lo
__device__ float    g_Vhi[BH * LL * DKK];   // [bh][l][dk] tf32-hi
__device__ float    g_Vlo[BH * LL * DKK];   // tf32-lo
__device__ float    g_O  [BH * LL * DKK];   // [bh][l][dk]
__device__ uint32_t g_MP [BB * LL * (LL / 32)];  // packed mask bits

// ---------------------------------------------------------------------------
// Helpers
// ---------------------------------------------------------------------------
__device__ __forceinline__ uint32_t f2tf32(float x) {
    uint32_t u;
    asm("cvt.rna.tf32.f32 %0, %1;" : "=r"(u) : "f"(x));
    return u;
}

// fast 2^t for t <= 0 (clamped at -120); err ~2e-8 (cephes degree-6)
__device__ __forceinline__ float exp2_fast(float t) {
    t = fmaxf(t, -120.f);
    int   i = __float2int_rd(t);
    float f = t - (float)i;
    float p =          1.535336188319500e-4f;
    p = fmaf(p, f, 1.339887440266574e-3f);
    p = fmaf(p, f, 9.618437357674640e-3f);
    p = fmaf(p, f, 5.550332471162809e-2f);
    p = fmaf(p, f, 2.402264791363012e-1f);
    p = fmaf(p, f, 6.931472028550421e-1f);
    p = fmaf(p, f, 1.0f);
    return __int_as_float((i + 127) << 23) * p;
}

// mma.sync m16n8k8 tf32: C += A x B   (A,B given as f32 values already
// tf32-rounded; bit patterns passed as .b32)
__device__ __forceinline__ void mma8(float c[4], const float a[4],
                                     float b0, float b1) {
    asm volatile(
        "mma.sync.aligned.m16n8k8.row.col.f32.tf32.tf32.f32 "
        "{%0,%1,%2,%3}, {%4,%5,%6,%7}, {%8,%9}, {%0,%1,%2,%3};"
        : "+f"(c[0]), "+f"(c[1]), "+f"(c[2]), "+f"(c[3])
        : "r"(__float_as_uint(a[0])), "r"(__float_as_uint(a[1])),
          "r"(__float_as_uint(a[2])), "r"(__float_as_uint(a[3])),
          "r"(__float_as_uint(b0)),  "r"(__float_as_uint(b1)));
}

// ---------------------------------------------------------------------------
// Mask packer: 32 int32 -> 1 bitmask word
// ---------------------------------------------------------------------------
__global__ __launch_bounds__(256)
void pack_mask_kernel(const int* __restrict__ mask)
{
    int w = blockIdx.x * 256 + threadIdx.x;        // 0 .. B*L*64-1
    const int4* p = (const int4*)(mask + (size_t)w * 32);
    uint32_t bits = 0;
    #pragma unroll
    for (int i = 0; i < 8; i++) {
        int4 m = p[i];
        bits |= (m.x != 0 ? 1u : 0u) << (i * 4 + 0);
        bits |= (m.y != 0 ? 1u : 0u) << (i * 4 + 1);
        bits |= (m.z != 0 ? 1u : 0u) << (i * 4 + 2);
        bits |= (m.w != 0 ? 1u : 0u) << (i * 4 + 3);
    }
    g_MP[w] = bits;
}

// ---------------------------------------------------------------------------
// QKV projection GEMM: 64x64 tile, Ktile=16, 256 threads, 4x4 microtile.
// z=0: Q -> g_Q fp32 [bh][l][dk]
// z=1: K -> g_Khi/g_Klo (tf32 split)
// z=2: V -> g_Vhi/g_Vlo (tf32 split)
// ---------------------------------------------------------------------------
__global__ __launch_bounds__(256)
void qkv_proj_kernel(const float* __restrict__ xq, const float* __restrict__ xk,
                     const float* __restrict__ xv,
                     const float* __restrict__ wq, const float* __restrict__ wk,
                     const float* __restrict__ wv,
                     const float* __restrict__ bq, const float* __restrict__ bk,
                     const float* __restrict__ bv)
{
    const float* A; const float* W; const float* bias;
    if (blockIdx.z == 0)      { A = xq; W = wq; bias = bq; }
    else if (blockIdx.z == 1) { A = xk; W = wk; bias = bk; }
    else                      { A = xv; W = wv; bias = bv; }

    __shared__ __align__(16) float As[16][64];
    __shared__ __align__(16) float Bs[16][64];

    const int tid  = threadIdx.x;
    const int tx   = tid & 15;
    const int ty   = tid >> 4;
    const int m0   = blockIdx.y * 64;
    const int n0   = blockIdx.x * 64;
    const int lrow = tid >> 2;
    const int lk4  = (tid & 3) << 2;
    const int brow = tid >> 4;
    const int bn4  = (tid & 15) << 2;

    float acc[4][4] = {};

    for (int k0 = 0; k0 < DD; k0 += 16) {
        float4 a4 = *(const float4*)(A + (size_t)(m0 + lrow) * DD + k0 + lk4);
        As[lk4 + 0][lrow] = a4.x;
        As[lk4 + 1][lrow] = a4.y;
        As[lk4 + 2][lrow] = a4.z;
        As[lk4 + 3][lrow] = a4.w;
        *(float4*)&Bs[brow][bn4] =
            *(const float4*)(W + (size_t)(k0 + brow) * DD + n0 + bn4);
        __syncthreads();
        #pragma unroll
        for (int k = 0; k < 16; k++) {
            float4 av = ((const float4*)As[k])[ty];
            float4 bv4 = ((const float4*)Bs[k])[tx];
            float a[4] = {av.x, av.y, av.z, av.w};
            float b[4] = {bv4.x, bv4.y, bv4.z, bv4.w};
            #pragma unroll
            for (int i = 0; i < 4; i++)
                #pragma unroll
                for (int j = 0; j < 4; j++)
                    acc[i][j] += a[i] * b[j];
        }
        __syncthreads();
    }

    const int n  = n0 + tx * 4;   // output feature (h*32+dk)
    const int h  = n >> 5;
    const int dk = n & 31;
    float4 b4 = *(const float4*)(bias + n);
    float bb[4] = {b4.x, b4.y, b4.z, b4.w};

    if (blockIdx.z == 0) {
        #pragma unroll
        for (int i = 0; i < 4; i++) {
            int m  = m0 + ty * 4 + i;
            int b_ = m >> 11;
            int l_ = m & (LL - 1);
            float4 o;
            o.x = acc[i][0] + bb[0]; o.y = acc[i][1] + bb[1];
            o.z = acc[i][2] + bb[2]; o.w = acc[i][3] + bb[3];
            *(float4*)(g_Q + (((size_t)(b_ * HH + h)) * LL + l_) * DKK + dk) = o;
        }
    } else {
        float* Dhi = (blockIdx.z == 1) ? g_Khi : g_Vhi;
        float* Dlo = (blockIdx.z == 1) ? g_Klo : g_Vlo;
        #pragma unroll
        for (int i = 0; i < 4; i++) {
            int m  = m0 + ty * 4 + i;
            int b_ = m >> 11;
            int l_ = m & (LL - 1);
            float v[4];
            v[0] = acc[i][0] + bb[0]; v[1] = acc[i][1] + bb[1];
            v[2] = acc[i][2] + bb[2]; v[3] = acc[i][3] + bb[3];
            float4 hi, lo;
            hi.x = __uint_as_float(f2tf32(v[0])); lo.x = __uint_as_float(f2tf32(v[0] - hi.x));
            hi.y = __uint_as_float(f2tf32(v[1])); lo.y = __uint_as_float(f2tf32(v[1] - hi.y));
            hi.z = __uint_as_float(f2tf32(v[2])); lo.z = __uint_as_float(f2tf32(v[2] - hi.z));
            hi.w = __uint_as_float(f2tf32(v[3])); lo.w = __uint_as_float(f2tf32(v[3] - hi.w));
            size_t off = (((size_t)(b_ * HH + h)) * LL + l_) * DKK + dk;
            *(float4*)(Dhi + off) = hi;
            *(float4*)(Dlo + off) = lo;
        }
    }
}

// ---------------------------------------------------------------------------
// FA2 attention with mma.sync tf32x3.
// CTA = 128 threads = 4 warps; warp owns 16 q-rows; CTA tile = 64 q x 64 k.
// K smem padded stride 36 (banks 4g+t distinct), V stride 40 (8t+g distinct).
// ---------------------------------------------------------------------------
#define KSTR 36
#define VSTR 40

__global__ __launch_bounds__(128, 2)
void attn_mma_kernel()
{
    __shared__ __align__(16) float sK[2][64 * KSTR];
    __shared__ __align__(16) float sV[2][64 * VSTR];

    const int tid  = threadIdx.x;
    const int warp = tid >> 5;
    const int lane = tid & 31;
    const int g    = lane >> 2;     // groupID 0..7
    const int t    = lane & 3;      // thread-in-group

    const int bh   = blockIdx.y;
    const int b_   = bh >> 4;
    const int qb   = blockIdx.x * 64 + warp * 16;
    const int row0 = qb + g;
    const int row1 = qb + g + 8;

    // ---- Q a-frags (hi/lo), scale*log2e folded in ----
    const float qscale = 0.17677669529663687f * 1.4426950408889634f;
    float qhi[4][4], qlo[4][4];
    {
        const float* Q0 = g_Q + ((size_t)bh * LL + row0) * DKK;
        const float* Q1 = g_Q + ((size_t)bh * LL + row1) * DKK;
        #pragma unroll
        for (int ks = 0; ks < 4; ks++) {
            float v[4];
            v[0] = Q0[8 * ks + t]     * qscale;
            v[1] = Q1[8 * ks + t]     * qscale;
            v[2] = Q0[8 * ks + t + 4] * qscale;
            v[3] = Q1[8 * ks + t + 4] * qscale;
            #pragma unroll
            for (int e = 0; e < 4; e++) {
                float h = __uint_as_float(f2tf32(v[e]));
                qhi[ks][e] = h;
                qlo[ks][e] = __uint_as_float(f2tf32(v[e] - h));
            }
        }
    }

    const float* gKh = g_Khi + (size_t)bh * LL * DKK;
    const float* gKl = g_Klo + (size_t)bh * LL * DKK;
    const float* gVh = g_Vhi + (size_t)bh * LL * DKK;
    const float* gVl = g_Vlo + (size_t)bh * LL * DKK;
    const uint32_t* mp0 = g_MP + ((size_t)(b_ * LL + row0)) * (LL / 32);
    const uint32_t* mp1 = g_MP + ((size_t)(b_ * LL + row1)) * (LL / 32);

    float m0 = -1e30f, m1 = -1e30f, l0 = 0.f, l1 = 0.f;
    float o[4][4] = {};

    for (int kt = 0; kt < LL; kt += 64) {
        // ---- fill smem K/V hi/lo tiles ----
        #pragma unroll
        for (int i = 0; i < 4; i++) {
            int e = i * 128 + tid;          // 0..511 float4s
            int r = e >> 3, c = (e & 7) << 2;
            size_t go = (size_t)(kt + r) * DKK + c;
            *(float4*)&sK[0][r * KSTR + c] = *(const float4*)(gKh + go);
            *(float4*)&sK[1][r * KSTR + c] = *(const float4*)(gKl + go);
            *(float4*)&sV[0][r * VSTR + c] = *(const float4*)(gVh + go);
            *(float4*)&sV[1][r * VSTR + c] = *(const float4*)(gVl + go);
        }
        __syncthreads();

        // ---- S = Q K^T (tf32x3), 8 n-blocks of 8 keys ----
        float s[8][4];
        #pragma unroll
        for (int nb = 0; nb < 8; nb++)
            s[nb][0] = s[nb][1] = s[nb][2] = s[nb][3] = 0.f;

        #pragma unroll
        for (int ks = 0; ks < 4; ks++) {
            #pragma unroll
            for (int nb = 0; nb < 8; nb++) {
                int base = (8 * nb + g) * KSTR + 8 * ks + t;
                float bh0 = sK[0][base];
                float bh1 = sK[0][base + 4];
                float bl0 = sK[1][base];
                float bl1 = sK[1][base + 4];
                mma8(s[nb], qhi[ks], bh0, bh1);
                mma8(s[nb], qhi[ks], bl0, bl1);
                mma8(s[nb], qlo[ks], bh0, bh1);
            }
        }

        // ---- mask ----
        uint32_t w0r0 = mp0[(kt >> 5)],     w1r0 = mp0[(kt >> 5) + 1];
        uint32_t w0r1 = mp1[(kt >> 5)],     w1r1 = mp1[(kt >> 5) + 1];
        #pragma unroll
        for (int nb = 0; nb < 8; nb++) {
            uint32_t wr0 = (nb < 4) ? w0r0 : w1r0;
            uint32_t wr1 = (nb < 4) ? w0r1 : w1r1;
            int c0 = (8 * nb + 2 * t) & 31;
            s[nb][0] = ((wr0 >> c0) & 1u)       ? s[nb][0] : -30000.f;
            s[nb][1] = ((wr0 >> (c0 + 1)) & 1u) ? s[nb][1] : -30000.f;
            s[nb][2] = ((wr1 >> c0) & 1u)       ? s[nb][2] : -30000.f;
            s[nb][3] = ((wr1 >> (c0 + 1)) & 1u) ? s[nb][3] : -30000.f;
        }

        // ---- row maxes (across quad) ----
        float mx0 = -1e30f, mx1 = -1e30f;
        #pragma unroll
        for (int nb = 0; nb < 8; nb++) {
            mx0 = fmaxf(mx0, fmaxf(s[nb][0], s[nb][1]));
            mx1 = fmaxf(mx1, fmaxf(s[nb][2], s[nb][3]));
        }
        mx0 = fmaxf(mx0, __shfl_xor_sync(0xffffffffu, mx0, 1));
        mx0 = fmaxf(mx0, __shfl_xor_sync(0xffffffffu, mx0, 2));
        mx1 = fmaxf(mx1, __shfl_xor_sync(0xffffffffu, mx1, 1));
        mx1 = fmaxf(mx1, __shfl_xor_sync(0xffffffffu, mx1, 2));

        float mn0 = fmaxf(m0, mx0);
        float mn1 = fmaxf(m1, mx1);
        float corr0 = exp2_fast(m0 - mn0);
        float corr1 = exp2_fast(m1 - mn1);
        m0 = mn0; m1 = mn1;
        l0 *= corr0; l1 *= corr1;
        #pragma unroll
        for (int nb = 0; nb < 4; nb++) {
            o[nb][0] *= corr0; o[nb][1] *= corr0;
            o[nb][2] *= corr1; o[nb][3] *= corr1;
        }

        // ---- p = 2^(s - m); accumulate row sums ----
        #pragma unroll
        for (int nb = 0; nb < 8; nb++) {
            s[nb][0] = exp2_fast(s[nb][0] - m0);
            s[nb][1] = exp2_fast(s[nb][1] - m0);
            s[nb][2] = exp2_fast(s[nb][2] - m1);
            s[nb][3] = exp2_fast(s[nb][3] - m1);
            l0 += s[nb][0] + s[nb][1];
            l1 += s[nb][2] + s[nb][3];
        }

        // ---- O += P V (tf32x3); convert C-layout -> A-layout via shfl ----
        const int src0 = (lane & ~3) | (t >> 1);
        const int src1 = src0 + 2;
        #pragma unroll
        for (int ks2 = 0; ks2 < 8; ks2++) {
            float x0 = __shfl_sync(0xffffffffu, s[ks2][0], src0);
            float x1 = __shfl_sync(0xffffffffu, s[ks2][1], src0);
            float x2 = __shfl_sync(0xffffffffu, s[ks2][2], src0);
            float x3 = __shfl_sync(0xffffffffu, s[ks2][3], src0);
            float y0 = __shfl_sync(0xffffffffu, s[ks2][0], src1);
            float y1 = __shfl_sync(0xffffffffu, s[ks2][1], src1);
            float y2 = __shfl_sync(0xffffffffu, s[ks2][2], src1);
            float y3 = __shfl_sync(0xffffffffu, s[ks2][3], src1);
            float a[4];
            a[0] = (t & 1) ? x1 : x0;   // (row0, col t)
            a[1] = (t & 1) ? x3 : x2;   // (row1, col t)
            a[2] = (t & 1) ? y1 : y0;   // (row0, col t+4)
            a[3] = (t & 1) ? y3 : y2;   // (row1, col t+4)
            float ah[4], al[4];
            #pragma unroll
            for (int e = 0; e < 4; e++) {
                ah[e] = __uint_as_float(f2tf32(a[e]));
                al[e] = __uint_as_float(f2tf32(a[e] - ah[e]));
            }
            #pragma unroll
            for (int nb2 = 0; nb2 < 4; nb2++) {
                int base = (8 * ks2 + t) * VSTR + 8 * nb2 + g;
                float vh0 = sV[0][base];
                float vh1 = sV[0][base + 4 * VSTR];
                float vl0 = sV[1][base];
                float vl1 = sV[1][base + 4 * VSTR];
                mma8(o[nb2], ah, vh0, vh1);
                mma8(o[nb2], ah, vl0, vl1);
                mma8(o[nb2], al, vh0, vh1);
            }
        }
        __syncthreads();
    }

    // ---- final: normalize and write ----
    l0 += __shfl_xor_sync(0xffffffffu, l0, 1);
    l0 += __shfl_xor_sync(0xffffffffu, l0, 2);
    l1 += __shfl_xor_sync(0xffffffffu, l1, 1);
    l1 += __shfl_xor_sync(0xffffffffu, l1, 2);
    float inv0 = 1.f / l0;
    float inv1 = 1.f / l1;

    float* O0 = g_O + ((size_t)bh * LL + row0) * DKK;
    float* O1 = g_O + ((size_t)bh * LL + row1) * DKK;
    #pragma unroll
    for (int nb2 = 0; nb2 < 4; nb2++) {
        float2 a0 = make_float2(o[nb2][0] * inv0, o[nb2][1] * inv0);
        float2 a1 = make_float2(o[nb2][2] * inv1, o[nb2][3] * inv1);
        *(float2*)(O0 + 8 * nb2 + 2 * t) = a0;
        *(float2*)(O1 + 8 * nb2 + 2 * t) = a1;
    }
}

// ---------------------------------------------------------------------------
// Output projection: out[b,l,:] = concat_heads(O)[b,l,:] @ Wo + bo
// ---------------------------------------------------------------------------
__global__ __launch_bounds__(256)
void out_proj_kernel(const float* __restrict__ wo, const float* __restrict__ bo,
                     float* __restrict__ out)
{
    __shared__ __align__(16) float As[16][64];
    __shared__ __align__(16) float Bs[16][64];

    const int tid  = threadIdx.x;
    const int tx   = tid & 15;
    const int ty   = tid >> 4;
    const int m0   = blockIdx.y * 64;
    const int n0   = blockIdx.x * 64;
    const int lrow = tid >> 2;
    const int lk4  = (tid & 3) << 2;
    const int brow = tid >> 4;
    const int bn4  = (tid & 15) << 2;

    const int m_  = m0 + lrow;
    const int ab  = m_ >> 11;
    const int al  = m_ & (LL - 1);

    float acc[4][4] = {};

    for (int k0 = 0; k0 < DD; k0 += 16) {
        int kk = k0 + lk4;
        int h  = kk >> 5;
        int dk = kk & 31;
        float4 a4 = *(const float4*)(g_O +
            (((size_t)(ab * HH + h)) * LL + al) * DKK + dk);
        As[lk4 + 0][lrow] = a4.x;
        As[lk4 + 1][lrow] = a4.y;
        As[lk4 + 2][lrow] = a4.z;
        As[lk4 + 3][lrow] = a4.w;
        *(float4*)&Bs[brow][bn4] =
            *(const float4*)(wo + (size_t)(k0 + brow) * DD + n0 + bn4);
        __syncthreads();
        #pragma unroll
        for (int k = 0; k < 16; k++) {
            float4 av = ((const float4*)As[k])[ty];
            float4 bv4 = ((const float4*)Bs[k])[tx];
            float a[4] = {av.x, av.y, av.z, av.w};
            float b[4] = {bv4.x, bv4.y, bv4.z, bv4.w};
            #pragma unroll
            for (int i = 0; i < 4; i++)
                #pragma unroll
                for (int j = 0; j < 4; j++)
                    acc[i][j] += a[i] * b[j];
        }
        __syncthreads();
    }

    const int n = n0 + tx * 4;
    float4 b4 = *(const float4*)(bo + n);
    #pragma unroll
    for (int i = 0; i < 4; i++) {
        int mr = m0 + ty * 4 + i;
        float4 oo;
        oo.x = acc[i][0] + b4.x;
        oo.y = acc[i][1] + b4.y;
        oo.z = acc[i][2] + b4.z;
        oo.w = acc[i][3] + b4.w;
        *(float4*)(out + (size_t)mr * DD + n) = oo;
    }
}

// ---------------------------------------------------------------------------
// Inputs: 0 q, 1 k, 2 v, 3 mask(int32), 4 is_training,
// 5 wq, 6 bq, 7 wk, 8 bk, 9 wv, 10 bv, 11 wo, 12 bo
// ---------------------------------------------------------------------------
extern "C" void kernel_launch(void* const* d_in, const int* in_sizes, int n_in,
                              void* d_out, int out_size)
{
    const float* q    = (const float*)d_in[0];
    const float* k    = (const float*)d_in[1];
    const float* v    = (const float*)d_in[2];
    const int*   mask = (const int*)  d_in[3];
    const float* wq   = (const float*)d_in[5];
    const float* bq   = (const float*)d_in[6];
    const float* wk   = (const float*)d_in[7];
    const float* bk   = (const float*)d_in[8];
    const float* wv   = (const float*)d_in[9];
    const float* bv   = (const float*)d_in[10];
    const float* wo   = (const float*)d_in[11];
    const float* bo   = (const float*)d_in[12];
    float* out = (float*)d_out;

    pack_mask_kernel<<<(BB * LL * (LL / 32)) / 256, 256>>>(mask);

    dim3 g1(DD / 64, MTOT / 64, 3);
    qkv_proj_kernel<<<g1, 256>>>(q, k, v, wq, wk, wv, bq, bk, bv);

    dim3 g2(LL / 64, BH);
    attn_mma_kernel<<<g2, 128>>>();

    dim3 g3(DD / 64, MTOT / 64);
    out_proj_kernel<<<g3, 256>>>(wo, bo, out);
}